// round 2
// baseline (speedup 1.0000x reference)
#include <cuda_runtime.h>
#include <math.h>

#define B_N   256
#define T_PAST 20
#define T_FUT  30
#define NT    256

// ---- shared memory layout (floats) ----
#define SM_WT1   0        // 4*32*36 = 4608   conv1 weights [kk][co][ci] stride 36
#define SM_WT2   4608     // 4608
#define SM_WT3   9216     // 4608
#define SM_WT0   13824    // 4*32*2 = 256     conv0 weights [kk][co][ci] stride 2
#define SM_CB    14080    // 128 (4 layers x 32 bias)
#define SM_DWIH  14208    // 96*35 = 3360 (padded stride 35)
#define SM_DWHH  17568    // 96*33 = 3168 (padded stride 33)
#define SM_WC    20736    // 128
#define SM_BC    20864    // 4
#define SM_A0    20868    // 25*32 = 800
#define SM_A1    21668    // 16*32 = 512
#define SM_A2    22180    // 9*32  = 288
#define SM_A3    22468    // 4*32  = 128
#define SM_LID   22596    // 6*6*2 = 72
#define SM_X     22668    // 34
#define SM_H     22702    // 32
#define SM_GI    22734    // 96
#define SM_GH    22830    // 96
#define SM_Y     22926    // 4 : y1[0],y1[1],y2[0],y2[1]
#define SM_LS    22930    // 4
#define SM_LD    22934    // 2
#define SM_TOTAL 22936
#define SMEM_BYTES (SM_TOTAL * 4)

__device__ float g_Wc[128];
__device__ float g_bc[4];

// Collapse the linear MLP: Wc = W2 @ W1 (4x32), bc = W2 @ b1 + b2 (4)
__global__ void combine_mlp_kernel(const float* __restrict__ w1,
                                   const float* __restrict__ b1,
                                   const float* __restrict__ w2,
                                   const float* __restrict__ b2)
{
    int tid = threadIdx.x;            // 128 threads
    int o = tid >> 5, i = tid & 31;
    const float* w2r = w2 + o * 512;
    float a0 = 0.f, a1 = 0.f, a2 = 0.f, a3 = 0.f;
    #pragma unroll 4
    for (int k = 0; k < 512; k += 4) {
        a0 = fmaf(w2r[k + 0], w1[(k + 0) * 32 + i], a0);
        a1 = fmaf(w2r[k + 1], w1[(k + 1) * 32 + i], a1);
        a2 = fmaf(w2r[k + 2], w1[(k + 2) * 32 + i], a2);
        a3 = fmaf(w2r[k + 3], w1[(k + 3) * 32 + i], a3);
    }
    g_Wc[tid] = (a0 + a1) + (a2 + a3);
    if (tid < 4) {
        float acc = b2[tid];
        for (int k = 0; k < 512; ++k) acc = fmaf(w2[tid * 512 + k], b1[k], acc);
        g_bc[tid] = acc;
    }
}

__device__ __forceinline__ float sigmoidf_(float x) {
    return 1.f / (1.f + expf(-x));
}

// One lazy conv layer of the pyramid.  OS = output side, IS = input side.
// warp per output cell (lane = output channel), up to 2 cells per warp so each
// weight float4 is loaded once and reused for both cells.
template <int OS, int IS>
__device__ __forceinline__ void conv_layer(const float* __restrict__ ain,
                                           float* __restrict__ aout,
                                           const float* __restrict__ wT,
                                           const float* __restrict__ bias,
                                           int fy, int fx, int tid)
{
    const int lane = tid & 31;
    const int wid  = tid >> 5;
    constexpr int NC = OS * OS;
    const int c0 = wid, c1 = wid + 8;
    if (c0 >= NC) return;
    const bool v1 = (c1 < NC);
    const int r0 = c0 / OS, x0 = c0 % OS;
    const int r1 = v1 ? (c1 / OS) : 0, x1 = v1 ? (c1 % OS) : 0;

    float p0 = 0.f, p1 = 0.f, p2 = 0.f, p3 = 0.f;
    float q0 = 0.f, q1 = 0.f, q2 = 0.f, q3 = 0.f;

    #pragma unroll
    for (int kk = 0; kk < 4; ++kk) {
        const int kh = kk >> 1, kw = kk & 1;
        const float* wp = wT + (kk * 32 + lane) * 36;
        const float* aA = ain + ((r0 + kh) * IS + (x0 + kw)) * 32;
        const float* aB = ain + ((r1 + kh) * IS + (x1 + kw)) * 32;
        #pragma unroll
        for (int q = 0; q < 8; ++q) {
            float4 wv = *(const float4*)(wp + q * 4);
            float4 av = *(const float4*)(aA + q * 4);
            p0 = fmaf(av.x, wv.x, p0);
            p1 = fmaf(av.y, wv.y, p1);
            p2 = fmaf(av.z, wv.z, p2);
            p3 = fmaf(av.w, wv.w, p3);
            if (v1) {
                float4 bv = *(const float4*)(aB + q * 4);
                q0 = fmaf(bv.x, wv.x, q0);
                q1 = fmaf(bv.y, wv.y, q1);
                q2 = fmaf(bv.z, wv.z, q2);
                q3 = fmaf(bv.w, wv.w, q3);
            }
        }
    }
    float o0 = fmaxf((p0 + p1) + (p2 + p3) + bias[lane], 0.f);
    if (fy + r0 > 99 || fx + x0 > 99) o0 = 0.f;   // zero padding beyond grid
    aout[c0 * 32 + lane] = o0;
    if (v1) {
        float o1 = fmaxf((q0 + q1) + (q2 + q3) + bias[lane], 0.f);
        if (fy + r1 > 99 || fx + x1 > 99) o1 = 0.f;
        aout[c1 * 32 + lane] = o1;
    }
}

extern __shared__ float sm[];

__global__ void __launch_bounds__(NT)
r2p2_kernel(const float* __restrict__ z,
            const float* __restrict__ pp,
            const float* __restrict__ lidar,
            const float* __restrict__ c0w, const float* __restrict__ c0b,
            const float* __restrict__ c1w, const float* __restrict__ c1b,
            const float* __restrict__ c2w, const float* __restrict__ c2b,
            const float* __restrict__ c3w, const float* __restrict__ c3b,
            const float* __restrict__ ewih, const float* __restrict__ ewhh,
            const float* __restrict__ ebih, const float* __restrict__ ebhh,
            const float* __restrict__ dwih, const float* __restrict__ dwhh,
            const float* __restrict__ dbih, const float* __restrict__ dbhh,
            float* __restrict__ out)
{
    const int b = blockIdx.x;
    const int tid = threadIdx.x;

    float* WT1 = sm + SM_WT1;  float* WT2 = sm + SM_WT2;  float* WT3 = sm + SM_WT3;
    float* WT0 = sm + SM_WT0;  float* CB  = sm + SM_CB;
    float* DWIH = sm + SM_DWIH; float* DWHH = sm + SM_DWHH;
    float* WC = sm + SM_WC;    float* BC = sm + SM_BC;
    float* A0 = sm + SM_A0;  float* A1 = sm + SM_A1;
    float* A2 = sm + SM_A2;  float* A3 = sm + SM_A3;
    float* LID = sm + SM_LID; float* X = sm + SM_X;  float* H = sm + SM_H;
    float* GI = sm + SM_GI;   float* GH = sm + SM_GH;
    float* Y  = sm + SM_Y;    float* LS = sm + SM_LS; float* LD = sm + SM_LD;

    // ---- load + transpose conv weights: HWIO (kk,ci,co) -> [kk][co][ci] ----
    {
        const float* srcs[3] = { c1w, c2w, c3w };
        float* dsts[3] = { WT1, WT2, WT3 };
        #pragma unroll
        for (int l = 0; l < 3; ++l) {
            const float* s = srcs[l]; float* d = dsts[l];
            for (int idx = tid; idx < 4096; idx += NT) {
                int co = idx & 31, ci = (idx >> 5) & 31, kk = idx >> 10;
                d[(kk * 32 + co) * 36 + ci] = s[idx];
            }
        }
        for (int idx = tid; idx < 256; idx += NT) {
            int co = idx & 31, ci = (idx >> 5) & 1, kk = idx >> 6;
            WT0[(kk * 32 + co) * 2 + ci] = c0w[idx];
        }
    }
    if (tid < 32) {
        CB[tid] = c0b[tid]; CB[32 + tid] = c1b[tid];
        CB[64 + tid] = c2b[tid]; CB[96 + tid] = c3b[tid];
    }
    for (int idx = tid; idx < 96 * 34; idx += NT) {
        int j = idx / 34, k = idx % 34;
        DWIH[j * 35 + k] = dwih[idx];
    }
    for (int idx = tid; idx < 96 * 32; idx += NT) {
        int j = idx >> 5, k = idx & 31;
        DWHH[j * 33 + k] = dwhh[idx];
    }
    if (tid < 128) WC[tid] = g_Wc[tid];
    if (tid < 4)   BC[tid] = g_bc[tid];
    if (tid < 32)  H[tid] = 0.f;
    __syncthreads();

    // ---- encoder GRU: 20 steps ----
    for (int t = 0; t < T_PAST; ++t) {
        float x0 = pp[(b * T_PAST + t) * 2];
        float x1 = pp[(b * T_PAST + t) * 2 + 1];
        if (tid < 96) {
            float gi = ebih[tid] + x0 * ewih[tid * 2] + x1 * ewih[tid * 2 + 1];
            float g0 = 0.f, g1 = 0.f, g2 = 0.f, g3 = 0.f;
            const float4* wr = (const float4*)(ewhh + tid * 32);
            #pragma unroll
            for (int k = 0; k < 8; ++k) {
                float4 wv = wr[k];
                g0 = fmaf(H[k * 4 + 0], wv.x, g0);
                g1 = fmaf(H[k * 4 + 1], wv.y, g1);
                g2 = fmaf(H[k * 4 + 2], wv.z, g2);
                g3 = fmaf(H[k * 4 + 3], wv.w, g3);
            }
            GI[tid] = gi;
            GH[tid] = ebhh[tid] + (g0 + g1) + (g2 + g3);
        }
        __syncthreads();
        if (tid < 32) {
            float r  = sigmoidf_(GI[tid] + GH[tid]);
            float zg = sigmoidf_(GI[32 + tid] + GH[32 + tid]);
            float n  = tanhf(GI[64 + tid] + r * GH[64 + tid]);
            H[tid] = (1.f - zg) * n + zg * H[tid];
        }
        __syncthreads();
    }
    if (tid < 2) {
        Y[tid]     = pp[(b * T_PAST + 19) * 2 + tid];   // y_{t-1}
        Y[2 + tid] = pp[(b * T_PAST + 18) * 2 + tid];   // y_{t-2}
    }
    __syncthreads();

    // ---- decoder: 30 autoregressive steps ----
    float logdet = 0.f;   // threads 0 and 1 each accumulate their dim
    for (int t = 0; t < T_FUT; ++t) {
        float q0c = Y[0], q1c = Y[1];
        float f0 = fminf(fmaxf(floorf(q0c), 0.f), 98.f);
        float f1 = fminf(fmaxf(floorf(q1c), 0.f), 98.f);
        int fy = (int)f0, fx = (int)f1;
        float ay = fminf(fmaxf(q0c - f0, 0.f), 1.f);
        float ax = fminf(fmaxf(q1c - f1, 0.f), 1.f);

        // 6x6x2 lidar patch (zero outside the grid)
        if (tid < 72) {
            int rr = tid / 12, cc = (tid % 12) >> 1, ci = tid & 1;
            int gy = fy + rr, gx = fx + cc;
            float v = 0.f;
            if (gy < 100 && gx < 100)
                v = lidar[((b * 100 + gy) * 100 + gx) * 2 + ci];
            LID[tid] = v;
        }
        __syncthreads();

        // layer0: 5x5x32, 2 input channels
        for (int idx = tid; idx < 800; idx += NT) {
            int co = idx & 31, cell = idx >> 5;
            int r = cell / 5, c = cell % 5;
            float acc = 0.f;
            #pragma unroll
            for (int kk = 0; kk < 4; ++kk) {
                int kh = kk >> 1, kw = kk & 1;
                const float* lp = LID + ((r + kh) * 6 + (c + kw)) * 2;
                const float* wp = WT0 + (kk * 32 + co) * 2;
                acc = fmaf(lp[0], wp[0], acc);
                acc = fmaf(lp[1], wp[1], acc);
            }
            acc = fmaxf(acc + CB[co], 0.f);
            if (fy + r > 99 || fx + c > 99) acc = 0.f;
            A0[cell * 32 + co] = acc;
        }
        __syncthreads();
        conv_layer<4, 5>(A0, A1, WT1, CB + 32, fy, fx, tid);
        __syncthreads();
        conv_layer<3, 4>(A1, A2, WT2, CB + 64, fy, fx, tid);
        __syncthreads();
        conv_layer<2, 3>(A2, A3, WT3, CB + 96, fy, fx, tid);
        __syncthreads();

        // bilinear over the 2x2 final cells; build GRU input x = [y1, interp]
        if (tid < 32) {
            float tl = A3[tid], tr = A3[32 + tid];
            float bl = A3[64 + tid], br = A3[96 + tid];
            float top = tl + ax * (tr - tl);
            float bot = bl + ax * (br - bl);
            X[2 + tid] = top + ay * (bot - top);
        }
        if (tid == 0) { X[0] = Y[0]; X[1] = Y[1]; }
        __syncthreads();

        // decoder GRU gates
        if (tid < 96) {
            float a0 = dbih[tid], a1 = 0.f;
            const float* wr = DWIH + tid * 35;
            #pragma unroll
            for (int k = 0; k < 34; k += 2) {
                a0 = fmaf(X[k], wr[k], a0);
                a1 = fmaf(X[k + 1], wr[k + 1], a1);
            }
            GI[tid] = a0 + a1;
            float g0 = 0.f, g1 = 0.f, g2 = 0.f, g3 = 0.f;
            const float* hr = DWHH + tid * 33;
            #pragma unroll
            for (int k = 0; k < 32; k += 4) {
                g0 = fmaf(H[k + 0], hr[k + 0], g0);
                g1 = fmaf(H[k + 1], hr[k + 1], g1);
                g2 = fmaf(H[k + 2], hr[k + 2], g2);
                g3 = fmaf(H[k + 3], hr[k + 3], g3);
            }
            GH[tid] = dbhh[tid] + (g0 + g1) + (g2 + g3);
        }
        __syncthreads();
        if (tid < 32) {
            float r  = sigmoidf_(GI[tid] + GH[tid]);
            float zg = sigmoidf_(GI[32 + tid] + GH[32 + tid]);
            float n  = tanhf(GI[64 + tid] + r * GH[64 + tid]);
            H[tid] = (1.f - zg) * n + zg * H[tid];
        }
        __syncthreads();
        // collapsed MLP head: ls = Wc @ h + bc  (4 outputs)
        if (tid < 4) {
            float a0 = BC[tid], a1 = 0.f, a2 = 0.f, a3 = 0.f;
            const float* wr = WC + tid * 32;
            #pragma unroll
            for (int k = 0; k < 32; k += 4) {
                a0 = fmaf(H[k + 0], wr[k + 0], a0);
                a1 = fmaf(H[k + 1], wr[k + 1], a1);
                a2 = fmaf(H[k + 2], wr[k + 2], a2);
                a3 = fmaf(H[k + 3], wr[k + 3], a3);
            }
            LS[tid] = (a0 + a1) + (a2 + a3);
        }
        __syncthreads();
        if (tid < 2) {
            float loc = LS[tid];
            float sp  = LS[2 + tid];
            float s   = (sp > 20.f) ? sp : log1pf(expf(sp));
            float zt  = z[(b * T_FUT + t) * 2 + tid];
            float yn  = 2.f * Y[tid] - Y[2 + tid] + loc + s * zt;
            out[(b * T_FUT + t) * 2 + tid] = yn;
            logdet += logf(s);
            Y[2 + tid] = Y[tid];
            Y[tid] = yn;
        }
        __syncthreads();
    }

    if (tid < 2) LD[tid] = logdet;
    __syncthreads();
    if (tid == 0) out[B_N * T_FUT * 2 + b] = LD[0] + LD[1];
}

extern "C" void kernel_launch(void* const* d_in, const int* in_sizes, int n_in,
                              void* d_out, int out_size)
{
    const float* z    = (const float*)d_in[0];
    const float* pp   = (const float*)d_in[1];
    const float* lid  = (const float*)d_in[2];
    const float* c0w  = (const float*)d_in[3];
    const float* c0b  = (const float*)d_in[4];
    const float* c1w  = (const float*)d_in[5];
    const float* c1b  = (const float*)d_in[6];
    const float* c2w  = (const float*)d_in[7];
    const float* c2b  = (const float*)d_in[8];
    const float* c3w  = (const float*)d_in[9];
    const float* c3b  = (const float*)d_in[10];
    const float* ewih = (const float*)d_in[11];
    const float* ewhh = (const float*)d_in[12];
    const float* ebih = (const float*)d_in[13];
    const float* ebhh = (const float*)d_in[14];
    const float* dwih = (const float*)d_in[15];
    const float* dwhh = (const float*)d_in[16];
    const float* dbih = (const float*)d_in[17];
    const float* dbhh = (const float*)d_in[18];
    const float* w1   = (const float*)d_in[19];
    const float* b1   = (const float*)d_in[20];
    const float* w2   = (const float*)d_in[21];
    const float* b2   = (const float*)d_in[22];
    float* out = (float*)d_out;

    cudaFuncSetAttribute(r2p2_kernel,
                         cudaFuncAttributeMaxDynamicSharedMemorySize, SMEM_BYTES);

    combine_mlp_kernel<<<1, 128>>>(w1, b1, w2, b2);
    r2p2_kernel<<<B_N, NT, SMEM_BYTES>>>(z, pp, lid,
        c0w, c0b, c1w, c1b, c2w, c2b, c3w, c3b,
        ewih, ewhh, ebih, ebhh, dwih, dwhh, dbih, dbhh, out);
}

// round 3
// speedup vs baseline: 1.3380x; 1.3380x over previous
#include <cuda_runtime.h>
#include <math.h>

#define B_N    256
#define T_PAST 20
#define T_FUT  30
#define NT     256

// ---- shared memory layout (float indices; all bases multiple of 4) ----
#define SM_WT1   0        // 4*32*36 = 4608   conv1 weights [kk][co][ci], row stride 36
#define SM_WT2   4608
#define SM_WT3   9216
#define SM_WT0   13824    // 4*32*2 = 256
#define SM_CB    14080    // 128 (4 layers x 32 bias)
#define SM_DWIH  14208    // 96*36 = 3456
#define SM_DWHH  17664    // 96*36 = 3456
#define SM_WC    21120    // 128
#define SM_BC    21248    // 4
#define SM_A0    21252    // 25*32 = 800
#define SM_A1    22052    // 16*32 = 512
#define SM_A2    22564    // 9*32  = 288
#define SM_A3    22852    // 4*32  = 128
#define SM_LID   22980    // 6*6*2 = 72
#define SM_X     23052    // 36 (34 used, padded)
#define SM_H     23088    // 32
#define SM_GI    23120    // 96
#define SM_GH    23216    // 96
#define SM_Y     23312    // 4 : y1[0],y1[1],y2[0],y2[1]
#define SM_LD    23316    // 2
#define SM_TOTAL 23320
#define SMEM_BYTES (SM_TOTAL * 4)

typedef unsigned long long ull;

__device__ float g_Wc[128];
__device__ float g_bc[4];

// packed f32x2 FMA: d = a*b + d (lanewise on the two fp32 halves)
__device__ __forceinline__ void ffma2(ull& d, ull a, ull b) {
    asm("fma.rn.f32x2 %0, %1, %2, %0;" : "+l"(d) : "l"(a), "l"(b));
}
__device__ __forceinline__ float hsum2(ull v) {
    float lo, hi;
    asm("mov.b64 {%0,%1}, %2;" : "=f"(lo), "=f"(hi) : "l"(v));
    return lo + hi;
}

__device__ __forceinline__ float sigmoidf_(float x) {
    return 1.f / (1.f + expf(-x));
}

// Collapse the linear MLP: Wc = W2 @ W1 (4x32), bc = W2 @ b1 + b2 (4)
__global__ void combine_mlp_kernel(const float* __restrict__ w1,
                                   const float* __restrict__ b1,
                                   const float* __restrict__ w2,
                                   const float* __restrict__ b2)
{
    int tid = threadIdx.x;            // 128 threads
    int o = tid >> 5, i = tid & 31;
    const float* w2r = w2 + o * 512;
    float a0 = 0.f, a1 = 0.f, a2 = 0.f, a3 = 0.f;
    #pragma unroll 4
    for (int k = 0; k < 512; k += 4) {
        a0 = fmaf(w2r[k + 0], w1[(k + 0) * 32 + i], a0);
        a1 = fmaf(w2r[k + 1], w1[(k + 1) * 32 + i], a1);
        a2 = fmaf(w2r[k + 2], w1[(k + 2) * 32 + i], a2);
        a3 = fmaf(w2r[k + 3], w1[(k + 3) * 32 + i], a3);
    }
    g_Wc[tid] = (a0 + a1) + (a2 + a3);
    if (tid < 4) {
        float acc = b2[tid];
        for (int k = 0; k < 512; ++k) acc = fmaf(w2[tid * 512 + k], b1[k], acc);
        g_bc[tid] = acc;
    }
}

// Lazy conv layer. OS = output side, IS = input side, CPW = cells per warp.
// warp w handles cells [w*CPW, w*CPW+CPW) (exact fit for our configs);
// lane = output channel. Each weight 16B load feeds CPW cells (4*CPW MACs).
template <int OS, int IS, int CPW>
__device__ __forceinline__ void conv_layerN(const float* __restrict__ ain,
                                            float* __restrict__ aout,
                                            const float* __restrict__ wT,
                                            const float* __restrict__ bias,
                                            int fy, int fx, int tid)
{
    const int lane = tid & 31;
    const int wid  = tid >> 5;
    constexpr int NC = OS * OS;
    constexpr int NW = NC / CPW;
    static_assert(NW * CPW == NC, "exact fit");
    if (wid >= NW) return;
    const int cb = wid * CPW;

    int rr[CPW], xx[CPW];
    #pragma unroll
    for (int c = 0; c < CPW; ++c) { rr[c] = (cb + c) / OS; xx[c] = (cb + c) % OS; }

    ull acc[CPW][2];
    #pragma unroll
    for (int c = 0; c < CPW; ++c) { acc[c][0] = 0ULL; acc[c][1] = 0ULL; }

    #pragma unroll
    for (int kk = 0; kk < 4; ++kk) {
        const int kh = kk >> 1, kw = kk & 1;
        const ulonglong2* wp = (const ulonglong2*)(wT + (kk * 32 + lane) * 36);
        const ulonglong2* ap[CPW];
        #pragma unroll
        for (int c = 0; c < CPW; ++c)
            ap[c] = (const ulonglong2*)(ain + ((rr[c] + kh) * IS + (xx[c] + kw)) * 32);
        #pragma unroll
        for (int q = 0; q < 8; ++q) {
            ulonglong2 wv = wp[q];           // lane-strided, 512B/warp
            #pragma unroll
            for (int c = 0; c < CPW; ++c) {
                ulonglong2 av = ap[c][q];    // warp-broadcast, 16B
                ffma2(acc[c][0], av.x, wv.x);
                ffma2(acc[c][1], av.y, wv.y);
            }
        }
    }
    const float bl = bias[lane];
    #pragma unroll
    for (int c = 0; c < CPW; ++c) {
        float o = hsum2(acc[c][0]) + hsum2(acc[c][1]) + bl;
        o = fmaxf(o, 0.f);
        if (fy + rr[c] > 99 || fx + xx[c] > 99) o = 0.f;   // zero padding
        aout[(cb + c) * 32 + lane] = o;
    }
}

extern __shared__ float sm[];

__global__ void __launch_bounds__(NT)
r2p2_kernel(const float* __restrict__ z,
            const float* __restrict__ pp,
            const float* __restrict__ lidar,
            const float* __restrict__ c0w, const float* __restrict__ c0b,
            const float* __restrict__ c1w, const float* __restrict__ c1b,
            const float* __restrict__ c2w, const float* __restrict__ c2b,
            const float* __restrict__ c3w, const float* __restrict__ c3b,
            const float* __restrict__ ewih, const float* __restrict__ ewhh,
            const float* __restrict__ ebih, const float* __restrict__ ebhh,
            const float* __restrict__ dwih, const float* __restrict__ dwhh,
            const float* __restrict__ dbih, const float* __restrict__ dbhh,
            float* __restrict__ out)
{
    const int b = blockIdx.x;
    const int tid = threadIdx.x;

    float* WT1 = sm + SM_WT1;  float* WT2 = sm + SM_WT2;  float* WT3 = sm + SM_WT3;
    float* WT0 = sm + SM_WT0;  float* CB  = sm + SM_CB;
    float* DWIH = sm + SM_DWIH; float* DWHH = sm + SM_DWHH;
    float* WC = sm + SM_WC;    float* BC = sm + SM_BC;
    float* A0 = sm + SM_A0;  float* A1 = sm + SM_A1;
    float* A2 = sm + SM_A2;  float* A3 = sm + SM_A3;
    float* LID = sm + SM_LID; float* X = sm + SM_X;  float* H = sm + SM_H;
    float* GI = sm + SM_GI;   float* GH = sm + SM_GH;
    float* Y  = sm + SM_Y;    float* LD = sm + SM_LD;

    // ---- load + transpose conv weights: HWIO (kk,ci,co) -> [kk][co][ci] ----
    {
        const float* srcs[3] = { c1w, c2w, c3w };
        float* dsts[3] = { WT1, WT2, WT3 };
        #pragma unroll
        for (int l = 0; l < 3; ++l) {
            const float* s = srcs[l]; float* d = dsts[l];
            for (int idx = tid; idx < 4096; idx += NT) {
                int co = idx & 31, ci = (idx >> 5) & 31, kk = idx >> 10;
                d[(kk * 32 + co) * 36 + ci] = s[idx];
            }
        }
        for (int idx = tid; idx < 256; idx += NT) {
            int co = idx & 31, ci = (idx >> 5) & 1, kk = idx >> 6;
            WT0[(kk * 32 + co) * 2 + ci] = c0w[idx];
        }
    }
    if (tid < 32) {
        CB[tid] = c0b[tid]; CB[32 + tid] = c1b[tid];
        CB[64 + tid] = c2b[tid]; CB[96 + tid] = c3b[tid];
    }
    for (int idx = tid; idx < 96 * 34; idx += NT) {
        int j = idx / 34, k = idx % 34;
        DWIH[j * 36 + k] = dwih[idx];
    }
    for (int idx = tid; idx < 96 * 32; idx += NT) {
        int j = idx >> 5, k = idx & 31;
        DWHH[j * 36 + k] = dwhh[idx];
    }
    if (tid < 128) WC[tid] = g_Wc[tid];
    if (tid < 4)   BC[tid] = g_bc[tid];
    if (tid < 32)  H[tid] = 0.f;
    if (tid >= 34 && tid < 36) X[tid] = 0.f;   // padding slot of X (unused)
    __syncthreads();

    // ---- encoder GRU: 20 steps ----
    for (int t = 0; t < T_PAST; ++t) {
        float x0 = pp[(b * T_PAST + t) * 2];
        float x1 = pp[(b * T_PAST + t) * 2 + 1];
        if (tid < 96) {
            float gi = ebih[tid] + x0 * ewih[tid * 2] + x1 * ewih[tid * 2 + 1];
            ull g0 = 0ULL, g1 = 0ULL;
            const float4* wr = (const float4*)(ewhh + tid * 32);
            const ulonglong2* hp = (const ulonglong2*)H;
            #pragma unroll
            for (int k = 0; k < 8; ++k) {
                float4 wf = wr[k];
                ulonglong2 wv = *(const ulonglong2*)&wf;
                ulonglong2 hv = hp[k];
                ffma2(g0, hv.x, wv.x);
                ffma2(g1, hv.y, wv.y);
            }
            GI[tid] = gi;
            GH[tid] = ebhh[tid] + hsum2(g0) + hsum2(g1);
        }
        __syncthreads();
        if (tid < 32) {
            float r  = sigmoidf_(GI[tid] + GH[tid]);
            float zg = sigmoidf_(GI[32 + tid] + GH[32 + tid]);
            float n  = tanhf(GI[64 + tid] + r * GH[64 + tid]);
            H[tid] = (1.f - zg) * n + zg * H[tid];
        }
        __syncthreads();
    }
    if (tid < 2) {
        Y[tid]     = pp[(b * T_PAST + 19) * 2 + tid];   // y_{t-1}
        Y[2 + tid] = pp[(b * T_PAST + 18) * 2 + tid];   // y_{t-2}
    }
    __syncthreads();

    // ---- decoder: 30 autoregressive steps ----
    float logdet = 0.f;   // threads 0 and 1 each accumulate their dim
    for (int t = 0; t < T_FUT; ++t) {
        float q0c = Y[0], q1c = Y[1];
        float f0 = fminf(fmaxf(floorf(q0c), 0.f), 98.f);
        float f1 = fminf(fmaxf(floorf(q1c), 0.f), 98.f);
        int fy = (int)f0, fx = (int)f1;
        float ay = fminf(fmaxf(q0c - f0, 0.f), 1.f);
        float ax = fminf(fmaxf(q1c - f1, 0.f), 1.f);

        // 6x6x2 lidar patch (zero outside the grid)
        if (tid < 72) {
            int rr = tid / 12, cc = (tid % 12) >> 1, ci = tid & 1;
            int gy = fy + rr, gx = fx + cc;
            float v = 0.f;
            if (gy < 100 && gx < 100)
                v = lidar[((b * 100 + gy) * 100 + gx) * 2 + ci];
            LID[tid] = v;
        }
        __syncthreads();

        // layer0: 5x5x32, 2 input channels (packed f32x2 over ci)
        for (int idx = tid; idx < 800; idx += NT) {
            int co = idx & 31, cell = idx >> 5;
            int r = cell / 5, c = cell % 5;
            ull acc = 0ULL;
            #pragma unroll
            for (int kk = 0; kk < 4; ++kk) {
                int kh = kk >> 1, kw = kk & 1;
                ull lv = *(const ull*)(LID + ((r + kh) * 6 + (c + kw)) * 2);
                ull wv = *(const ull*)(WT0 + (kk * 32 + co) * 2);
                ffma2(acc, lv, wv);
            }
            float o = fmaxf(hsum2(acc) + CB[co], 0.f);
            if (fy + r > 99 || fx + c > 99) o = 0.f;
            A0[cell * 32 + co] = o;
        }
        __syncthreads();
        conv_layerN<4, 5, 4>(A0, A1, WT1, CB + 32, fy, fx, tid);
        __syncthreads();
        conv_layerN<3, 4, 3>(A1, A2, WT2, CB + 64, fy, fx, tid);
        __syncthreads();
        conv_layerN<2, 3, 2>(A2, A3, WT3, CB + 96, fy, fx, tid);
        __syncthreads();

        // bilinear over the 2x2 final cells; X = [y1, interp]
        if (tid < 32) {
            float tl = A3[tid], tr = A3[32 + tid];
            float bl = A3[64 + tid], br = A3[96 + tid];
            float top = tl + ax * (tr - tl);
            float bot = bl + ax * (br - bl);
            X[2 + tid] = top + ay * (bot - top);
            if (tid < 2) X[tid] = Y[tid];
        }
        __syncthreads();

        // decoder GRU gates (packed f32x2)
        if (tid < 96) {
            ull a0 = 0ULL, a1 = 0ULL;
            const ulonglong2* wr = (const ulonglong2*)(DWIH + tid * 36);
            const ulonglong2* xp = (const ulonglong2*)X;
            #pragma unroll
            for (int k = 0; k < 8; ++k) {
                ulonglong2 wv = wr[k];
                ulonglong2 xv = xp[k];
                ffma2(a0, xv.x, wv.x);
                ffma2(a1, xv.y, wv.y);
            }
            ull wl = *(const ull*)(DWIH + tid * 36 + 32);
            ull xl = *(const ull*)(X + 32);
            ffma2(a0, xl, wl);
            GI[tid] = dbih[tid] + hsum2(a0) + hsum2(a1);

            ull g0 = 0ULL, g1 = 0ULL;
            const ulonglong2* hr = (const ulonglong2*)(DWHH + tid * 36);
            const ulonglong2* hp = (const ulonglong2*)H;
            #pragma unroll
            for (int k = 0; k < 8; ++k) {
                ulonglong2 wv = hr[k];
                ulonglong2 hv = hp[k];
                ffma2(g0, hv.x, wv.x);
                ffma2(g1, hv.y, wv.y);
            }
            GH[tid] = dbhh[tid] + hsum2(g0) + hsum2(g1);
        }
        __syncthreads();

        // warp 0: hidden update, head, y-update — no extra block barriers
        if (tid < 32) {
            float r  = sigmoidf_(GI[tid] + GH[tid]);
            float zg = sigmoidf_(GI[32 + tid] + GH[32 + tid]);
            float n  = tanhf(GI[64 + tid] + r * GH[64 + tid]);
            H[tid] = (1.f - zg) * n + zg * H[tid];
            __syncwarp();
            if (tid < 2) {
                const ulonglong2* hp = (const ulonglong2*)H;
                const ulonglong2* w0 = (const ulonglong2*)(WC + tid * 32);
                const ulonglong2* w1 = (const ulonglong2*)(WC + (tid + 2) * 32);
                ull l0 = 0ULL, l1 = 0ULL, s0 = 0ULL, s1 = 0ULL;
                #pragma unroll
                for (int k = 0; k < 8; ++k) {
                    ulonglong2 hv = hp[k];
                    ulonglong2 wa = w0[k];
                    ulonglong2 wb = w1[k];
                    ffma2(l0, hv.x, wa.x); ffma2(l1, hv.y, wa.y);
                    ffma2(s0, hv.x, wb.x); ffma2(s1, hv.y, wb.y);
                }
                float loc = BC[tid] + hsum2(l0) + hsum2(l1);
                float sp  = BC[tid + 2] + hsum2(s0) + hsum2(s1);
                float s   = (sp > 20.f) ? sp : log1pf(expf(sp));
                float zt  = z[(b * T_FUT + t) * 2 + tid];
                float yn  = 2.f * Y[tid] - Y[2 + tid] + loc + s * zt;
                out[(b * T_FUT + t) * 2 + tid] = yn;
                logdet += logf(s);
                Y[2 + tid] = Y[tid];
                Y[tid] = yn;
            }
        }
        __syncthreads();   // Y/H visible for next step
    }

    if (tid < 2) LD[tid] = logdet;
    __syncthreads();
    if (tid == 0) out[B_N * T_FUT * 2 + b] = LD[0] + LD[1];
}

extern "C" void kernel_launch(void* const* d_in, const int* in_sizes, int n_in,
                              void* d_out, int out_size)
{
    const float* z    = (const float*)d_in[0];
    const float* pp   = (const float*)d_in[1];
    const float* lid  = (const float*)d_in[2];
    const float* c0w  = (const float*)d_in[3];
    const float* c0b  = (const float*)d_in[4];
    const float* c1w  = (const float*)d_in[5];
    const float* c1b  = (const float*)d_in[6];
    const float* c2w  = (const float*)d_in[7];
    const float* c2b  = (const float*)d_in[8];
    const float* c3w  = (const float*)d_in[9];
    const float* c3b  = (const float*)d_in[10];
    const float* ewih = (const float*)d_in[11];
    const float* ewhh = (const float*)d_in[12];
    const float* ebih = (const float*)d_in[13];
    const float* ebhh = (const float*)d_in[14];
    const float* dwih = (const float*)d_in[15];
    const float* dwhh = (const float*)d_in[16];
    const float* dbih = (const float*)d_in[17];
    const float* dbhh = (const float*)d_in[18];
    const float* w1   = (const float*)d_in[19];
    const float* b1   = (const float*)d_in[20];
    const float* w2   = (const float*)d_in[21];
    const float* b2   = (const float*)d_in[22];
    float* out = (float*)d_out;

    cudaFuncSetAttribute(r2p2_kernel,
                         cudaFuncAttributeMaxDynamicSharedMemorySize, SMEM_BYTES);

    combine_mlp_kernel<<<1, 128>>>(w1, b1, w2, b2);
    r2p2_kernel<<<B_N, NT, SMEM_BYTES>>>(z, pp, lid,
        c0w, c0b, c1w, c1b, c2w, c2b, c3w, c3b,
        ewih, ewhh, ebih, ebhh, dwih, dwhh, dbih, dbhh, out);
}